// round 8
// baseline (speedup 1.0000x reference)
#include <cuda_runtime.h>
#include <math.h>
#include <stdint.h>

// ---------------------------------------------------------------------------
// Problem constants
// ---------------------------------------------------------------------------
#define BATCH 32
#define IMG   224
#define PATCH 16
#define DM    768
#define NH    12
#define HS    64
#define NL    12
#define TB    32
#define MLPD  3072
#define AOUT  7
#define NPATCH 196
#define SEQ   426
#define TOK   (BATCH*SEQ)   // 13632
#define SCALE 0.03608439182435161f  // 768^-0.5

// ---------------------------------------------------------------------------
// Scratch
// ---------------------------------------------------------------------------
__device__ float g_X  [TOK*DM];
__device__ float g_XN [TOK*DM];
__device__ float g_Q  [TOK*DM];
__device__ float g_K  [TOK*DM];
__device__ float g_V  [TOK*DM];
__device__ float g_ATT[TOK*DM];
__device__ float g_H  [TOK*MLPD];
__device__ float g_P  [BATCH*NPATCH*DM];
__device__ float g_CLS[BATCH*DM];
__device__ float g_HID[BATCH*4*DM];

// ---------------------------------------------------------------------------
// TF32 helpers
// ---------------------------------------------------------------------------
__device__ __forceinline__ uint32_t f2tf32(float f) {
    uint32_t r;
    asm("cvt.rna.tf32.f32 %0, %1;" : "=r"(r) : "f"(f));
    return r;
}

__device__ __forceinline__ void mma_tf32(float (&d)[4], const uint32_t (&a)[4],
                                         const uint32_t (&b)[2]) {
    asm volatile(
        "mma.sync.aligned.m16n8k8.row.col.f32.tf32.tf32.f32 "
        "{%0,%1,%2,%3}, {%4,%5,%6,%7}, {%8,%9}, {%0,%1,%2,%3};"
        : "+f"(d[0]), "+f"(d[1]), "+f"(d[2]), "+f"(d[3])
        : "r"(a[0]), "r"(a[1]), "r"(a[2]), "r"(a[3]), "r"(b[0]), "r"(b[1]));
}

// ---------------------------------------------------------------------------
// DUAL-PIPE GEMM: tile 128 x 192 = 128 cols tensor(mma, tf32) + 64 cols FFMA
// (fp32). 384 threads: warps 0-7 mma (2/SMSP), warps 8-11 FFMA (1/SMSP).
// Both pipes saturate at ~2048 cyc/tile/SMSP. Double-buffered smem,
// register-staged loads. Requires N % 192 == 0, K % 16 == 0.
// ---------------------------------------------------------------------------
#define DUAL_SMEM 66560

template<bool BHEAD, bool RELU, bool ACCUM, bool BIAS>
__global__ void __launch_bounds__(384)
gemm_dual(const float* __restrict__ A, const float* __restrict__ B,
          float* __restrict__ C, const float* __restrict__ bias,
          int M, int N, int K, int lda, int ldb, int ldc, float alpha)
{
    extern __shared__ char dsm[];
    uint32_t* As = (uint32_t*)dsm;            // [2][128][20] tf32 r-major
    uint32_t* Bs = As + 2*128*20;             // [2][128][20] tf32 n-major
    float*    Af = (float*)(Bs + 2*128*20);   // [2][16][132] fp32 k-major
    float*    Bf = Af + 2*16*132;             // [2][16][68]  fp32 k-major

    const int tid    = threadIdx.x;
    const int row0   = blockIdx.y * 128;
    const int col0   = blockIdx.x * 192;
    const int ntiles = K >> 4;

    if (tid < 256) {
        // ======================= MMA half (cols 0..127) =====================
        const int wid = tid >> 5, lane = tid & 31;
        const int g = lane >> 2, tg = lane & 3;
        const int warp_m = (wid & 3) * 32;
        const int warp_n = (wid >> 2) * 64;

        float acc[2][8][4] = {};
        float va[2][4];
        float vb[8];

        auto load_regs = [&](int kt) {
            #pragma unroll
            for (int i = 0; i < 2; i++) {
                int idx = tid + i * 256;
                int r = idx >> 2, kq = (idx & 3) * 4;
                int gr = row0 + r;
                const float* ap = A + (long long)gr * lda + kt + kq;
                #pragma unroll
                for (int j = 0; j < 4; j++) va[i][j] = (gr < M) ? ap[j] : 0.f;
            }
            #pragma unroll
            for (int i = 0; i < 8; i++) {
                int idx = tid + i * 256;
                int n = idx & 127, k = idx >> 7;
                int gn = col0 + n, gk = kt + k;
                long long off;
                if (BHEAD) off = (long long)(gn >> 6) * ldb + (long long)gk * 64 + (gn & 63);
                else       off = (long long)gk * ldb + gn;
                vb[i] = B[off];
            }
        };
        auto store_smem = [&](int st) {
            uint32_t* as = As + st * 2560;
            uint32_t* bs = Bs + st * 2560;
            #pragma unroll
            for (int i = 0; i < 2; i++) {
                int idx = tid + i * 256;
                int r = idx >> 2, kq = (idx & 3) * 4;
                #pragma unroll
                for (int j = 0; j < 4; j++) as[r * 20 + kq + j] = f2tf32(va[i][j]);
            }
            #pragma unroll
            for (int i = 0; i < 8; i++) {
                int idx = tid + i * 256;
                int n = idx & 127, k = idx >> 7;
                bs[n * 20 + k] = f2tf32(vb[i]);
            }
        };

        load_regs(0); store_smem(0); __syncthreads();
        int cur = 0;
        for (int t = 0; t < ntiles; t++) {
            if (t + 1 < ntiles) load_regs((t + 1) << 4);
            const uint32_t* as = As + cur * 2560;
            const uint32_t* bs = Bs + cur * 2560;
            #pragma unroll
            for (int kk = 0; kk < 16; kk += 8) {
                uint32_t af[2][4];
                #pragma unroll
                for (int mt = 0; mt < 2; mt++) {
                    int rs = warp_m + mt * 16 + g;
                    af[mt][0] = as[rs * 20 + kk + tg];
                    af[mt][1] = as[(rs + 8) * 20 + kk + tg];
                    af[mt][2] = as[rs * 20 + kk + tg + 4];
                    af[mt][3] = as[(rs + 8) * 20 + kk + tg + 4];
                }
                uint32_t bfr[8][2];
                #pragma unroll
                for (int nt = 0; nt < 8; nt++) {
                    int cs = warp_n + nt * 8 + g;
                    bfr[nt][0] = bs[cs * 20 + kk + tg];
                    bfr[nt][1] = bs[cs * 20 + kk + tg + 4];
                }
                #pragma unroll
                for (int mt = 0; mt < 2; mt++)
                    #pragma unroll
                    for (int nt = 0; nt < 8; nt++)
                        mma_tf32(acc[mt][nt], af[mt], bfr[nt]);
            }
            if (t + 1 < ntiles) { store_smem(cur ^ 1); __syncthreads(); cur ^= 1; }
        }

        #pragma unroll
        for (int mt = 0; mt < 2; mt++) {
            #pragma unroll
            for (int nt = 0; nt < 8; nt++) {
                int r_base = row0 + warp_m + mt * 16 + g;
                int c_base = col0 + warp_n + nt * 8 + tg * 2;
                #pragma unroll
                for (int h = 0; h < 2; h++) {
                    int r = r_base + h * 8;
                    if (r >= M) continue;
                    #pragma unroll
                    for (int j = 0; j < 2; j++) {
                        int c = c_base + j;
                        float v = acc[mt][nt][h * 2 + j] * alpha;
                        if (BIAS) v += bias[c];
                        long long ci = (long long)r * ldc + c;
                        if (ACCUM) v += C[ci];
                        if (RELU)  v = fmaxf(v, 0.f);
                        C[ci] = v;
                    }
                }
            }
        }
    } else {
        // ====================== FFMA half (cols 128..191) ===================
        const int ft  = tid - 256;          // 0..127
        const int rg  = ft & 15;            // output rows rg*8..+7
        const int cg  = ft >> 4;            // output cols 128+cg*8..+7
        const int lr  = (ft & 31) * 4;      // loader rows
        const int lkq = (ft >> 5) * 4;      // loader ks for A
        const int lc  = ft & 63;            // loader col for Bf
        const int lkh = (ft >> 6) * 8;      // loader ks for Bf

        float facc[8][8] = {};
        float vaf[4][4];
        float vbf[8];

        auto load_regs = [&](int kt) {
            #pragma unroll
            for (int i = 0; i < 4; i++) {
                int gr = row0 + lr + i;
                if (gr < M) {
                    float4 tq = *(const float4*)(A + (long long)gr * lda + kt + lkq);
                    vaf[i][0] = tq.x; vaf[i][1] = tq.y; vaf[i][2] = tq.z; vaf[i][3] = tq.w;
                } else {
                    vaf[i][0] = vaf[i][1] = vaf[i][2] = vaf[i][3] = 0.f;
                }
            }
            #pragma unroll
            for (int j = 0; j < 8; j++) {
                int gk = kt + lkh + j;
                int gn = col0 + 128 + lc;
                long long off;
                if (BHEAD) off = (long long)(gn >> 6) * ldb + (long long)gk * 64 + (gn & 63);
                else       off = (long long)gk * ldb + gn;
                vbf[j] = B[off];
            }
        };
        auto store_smem = [&](int st) {
            float* af = Af + st * 2112;
            float* bf = Bf + st * 1088;
            #pragma unroll
            for (int i = 0; i < 4; i++)
                #pragma unroll
                for (int j = 0; j < 4; j++)
                    af[(lkq + j) * 132 + lr + i] = vaf[i][j];
            #pragma unroll
            for (int j = 0; j < 8; j++)
                bf[(lkh + j) * 68 + lc] = vbf[j];
        };

        load_regs(0); store_smem(0); __syncthreads();
        int cur = 0;
        for (int t = 0; t < ntiles; t++) {
            if (t + 1 < ntiles) load_regs((t + 1) << 4);
            const float* af = Af + cur * 2112;
            const float* bf = Bf + cur * 1088;
            #pragma unroll
            for (int k = 0; k < 16; k++) {
                float4 a0 = *(const float4*)&af[k * 132 + rg * 8];
                float4 a1 = *(const float4*)&af[k * 132 + rg * 8 + 4];
                float4 b0 = *(const float4*)&bf[k * 68 + cg * 8];
                float4 b1 = *(const float4*)&bf[k * 68 + cg * 8 + 4];
                float av[8] = {a0.x, a0.y, a0.z, a0.w, a1.x, a1.y, a1.z, a1.w};
                float bv[8] = {b0.x, b0.y, b0.z, b0.w, b1.x, b1.y, b1.z, b1.w};
                #pragma unroll
                for (int i = 0; i < 8; i++)
                    #pragma unroll
                    for (int j = 0; j < 8; j++)
                        facc[i][j] += av[i] * bv[j];
            }
            if (t + 1 < ntiles) { store_smem(cur ^ 1); __syncthreads(); cur ^= 1; }
        }

        #pragma unroll
        for (int i = 0; i < 8; i++) {
            int r = row0 + rg * 8 + i;
            if (r >= M) continue;
            #pragma unroll
            for (int j = 0; j < 8; j++) {
                int c = col0 + 128 + cg * 8 + j;
                float v = facc[i][j] * alpha;
                if (BIAS) v += bias[c];
                long long ci = (long long)r * ldc + c;
                if (ACCUM) v += C[ci];
                if (RELU)  v = fmaxf(v, 0.f);
                C[ci] = v;
            }
        }
    }
}

// ---------------------------------------------------------------------------
// Small TF32 GEMM (R2 version) — only for the final tiny action-head GEMM.
// ---------------------------------------------------------------------------
#define SLD 20

template<int BN, bool TRANSB, bool BHEAD, bool RELU, bool ACCUM, bool BIAS>
__global__ void __launch_bounds__(256)
gemm_tf32(const float* __restrict__ A, const float* __restrict__ B,
          float* __restrict__ C, const float* __restrict__ bias,
          int M, int N, int K, int lda, int ldb, int ldc, float alpha,
          int ndiv, long long s1A, long long s2A, long long s1B, long long s2B,
          long long s1C, long long s2C)
{
    constexpr int NT = (BN / 2) / 8;
    __shared__ uint32_t As[128][SLD];
    __shared__ uint32_t Bs[BN][SLD];

    const int z  = blockIdx.z;
    const int z1 = z / ndiv, z2 = z % ndiv;
    A += (long long)z1 * s1A + (long long)z2 * s2A;
    B += (long long)z1 * s1B + (long long)z2 * s2B;
    C += (long long)z1 * s1C + (long long)z2 * s2C;

    const int tid    = threadIdx.x;
    const int wid    = tid >> 5;
    const int lane   = tid & 31;
    const int g      = lane >> 2;
    const int tg     = lane & 3;
    const int warp_m = (wid & 3) * 32;
    const int warp_n = (wid >> 2) * (BN / 2);
    const int row0   = blockIdx.y * 128;
    const int col0   = blockIdx.x * BN;

    float acc[2][NT][4];
    #pragma unroll
    for (int mt = 0; mt < 2; mt++)
        #pragma unroll
        for (int nt = 0; nt < NT; nt++)
            #pragma unroll
            for (int i = 0; i < 4; i++) acc[mt][nt][i] = 0.f;

    for (int kt = 0; kt < K; kt += 16) {
        #pragma unroll
        for (int i = 0; i < 2; i++) {
            int idx = tid + i * 256;
            int r   = idx >> 2;
            int kq  = (idx & 3) * 4;
            int gr  = row0 + r;
            const float* ap = A + (long long)gr * lda + kt + kq;
            #pragma unroll
            for (int j = 0; j < 4; j++) {
                int gk = kt + kq + j;
                float v = (gr < M && gk < K) ? ap[j] : 0.f;
                As[r][kq + j] = f2tf32(v);
            }
        }
        {
            constexpr int ELEMS = BN * 16 / 256;
            #pragma unroll
            for (int i = 0; i < ELEMS; i++) {
                int idx = tid + i * 256;
                int n, k;
                if (TRANSB) { k = idx & 15; n = idx >> 4; }
                else        { n = idx % BN; k = idx / BN; }
                int gk = kt + k, gn = col0 + n;
                float v = 0.f;
                if (gk < K && gn < N) {
                    long long off;
                    if (TRANSB)      off = (long long)gn * ldb + gk;
                    else if (BHEAD)  off = (long long)(gn >> 6) * ldb + (long long)gk * 64 + (gn & 63);
                    else             off = (long long)gk * ldb + gn;
                    v = B[off];
                }
                Bs[n][k] = f2tf32(v);
            }
        }
        __syncthreads();

        #pragma unroll
        for (int kk = 0; kk < 16; kk += 8) {
            uint32_t af[2][4];
            #pragma unroll
            for (int mt = 0; mt < 2; mt++) {
                int rs = warp_m + mt * 16 + g;
                af[mt][0] = As[rs][kk + tg];
                af[mt][1] = As[rs + 8][kk + tg];
                af[mt][2] = As[rs][kk + tg + 4];
                af[mt][3] = As[rs + 8][kk + tg + 4];
            }
            uint32_t bf[NT][2];
            #pragma unroll
            for (int nt = 0; nt < NT; nt++) {
                int cs = warp_n + nt * 8 + g;
                bf[nt][0] = Bs[cs][kk + tg];
                bf[nt][1] = Bs[cs][kk + tg + 4];
            }
            #pragma unroll
            for (int mt = 0; mt < 2; mt++)
                #pragma unroll
                for (int nt = 0; nt < NT; nt++)
                    mma_tf32(acc[mt][nt], af[mt], bf[nt]);
        }
        __syncthreads();
    }

    #pragma unroll
    for (int mt = 0; mt < 2; mt++) {
        #pragma unroll
        for (int nt = 0; nt < NT; nt++) {
            int r_base = row0 + warp_m + mt * 16 + g;
            int c_base = col0 + warp_n + nt * 8 + tg * 2;
            #pragma unroll
            for (int h = 0; h < 2; h++) {
                int r = r_base + h * 8;
                if (r >= M) continue;
                #pragma unroll
                for (int j = 0; j < 2; j++) {
                    int c = c_base + j;
                    if (c >= N) continue;
                    float v = acc[mt][nt][h * 2 + j] * alpha;
                    if (BIAS) v += bias[c];
                    long long ci = (long long)r * ldc + c;
                    if (ACCUM) v += C[ci];
                    if (RELU)  v = fmaxf(v, 0.f);
                    C[ci] = v;
                }
            }
        }
    }
}

// ---------------------------------------------------------------------------
// Fused flash attention (R7 version — proven).
// ---------------------------------------------------------------------------
#define FLASH_SMEM_WORDS (8704 + 4352 + 4352 + 8704 + 256 + 256 + 128 + 128)

__global__ void __launch_bounds__(256)
flash_attn_k(const float* __restrict__ Qf, const float* __restrict__ Kf,
             const float* __restrict__ Vf, float* __restrict__ ATT)
{
    extern __shared__ uint32_t fsm[];
    uint32_t* Qs   = fsm;
    uint32_t* Ks   = Qs + 128 * 68;
    uint32_t* Vs   = Ks + 64 * 68;
    uint32_t* Ps   = Vs + 64 * 68;
    float* red_m   = (float*)(Ps + 128 * 68);
    float* red_l   = red_m + 256;
    float* row_m   = red_l + 256;
    float* row_l   = row_m + 128;

    const int z  = blockIdx.y;
    const int b  = z / NH, h = z % NH;
    const int q0 = blockIdx.x * 128;

    const int tid  = threadIdx.x;
    const int wid  = tid >> 5;
    const int lane = tid & 31;
    const int g    = lane >> 2;
    const int tg   = lane & 3;
    const int warp_m = (wid & 3) * 32;
    const int warp_n = (wid >> 2) * 32;
    const int colgrp = wid >> 2;

    for (int i = tid; i < 128 * 64; i += 256) {
        int r = i >> 6, d = i & 63;
        int t = q0 + r;
        float v = (t < SEQ) ? Qf[((long long)(b * SEQ + t)) * DM + h * HS + d] : 0.f;
        Qs[r * 68 + d] = f2tf32(v);
    }
    if (tid < 128) { row_m[tid] = -1e30f; row_l[tid] = 0.f; }

    float oacc[2][4][4] = {};
    __syncthreads();

    for (int kt0 = 0; kt0 < SEQ; kt0 += 64) {
        for (int i = tid; i < 64 * 64; i += 256) {
            int kk = i >> 6, d = i & 63;
            int t = kt0 + kk;
            float kv = 0.f, vv = 0.f;
            if (t < SEQ) {
                long long base = ((long long)(b * SEQ + t)) * DM + h * HS + d;
                kv = Kf[base];
                vv = Vf[base];
            }
            Ks[kk * 68 + d] = f2tf32(kv);
            Vs[d * 68 + kk] = f2tf32(vv);
        }
        __syncthreads();

        float sacc[2][4][4] = {};
        #pragma unroll
        for (int ks = 0; ks < 8; ks++) {
            const int kk = ks * 8;
            uint32_t af[2][4];
            #pragma unroll
            for (int mt = 0; mt < 2; mt++) {
                int rs = warp_m + mt * 16 + g;
                af[mt][0] = Qs[rs * 68 + kk + tg];
                af[mt][1] = Qs[(rs + 8) * 68 + kk + tg];
                af[mt][2] = Qs[rs * 68 + kk + tg + 4];
                af[mt][3] = Qs[(rs + 8) * 68 + kk + tg + 4];
            }
            uint32_t bf[4][2];
            #pragma unroll
            for (int nt = 0; nt < 4; nt++) {
                int cs = warp_n + nt * 8 + g;
                bf[nt][0] = Ks[cs * 68 + kk + tg];
                bf[nt][1] = Ks[cs * 68 + kk + tg + 4];
            }
            #pragma unroll
            for (int mt = 0; mt < 2; mt++)
                #pragma unroll
                for (int nt = 0; nt < 4; nt++)
                    mma_tf32(sacc[mt][nt], af[mt], bf[nt]);
        }

        #pragma unroll
        for (int mt = 0; mt < 2; mt++) {
            #pragma unroll
            for (int hh = 0; hh < 2; hh++) {
                float pm = -1e30f;
                #pragma unroll
                for (int nt = 0; nt < 4; nt++) {
                    #pragma unroll
                    for (int j = 0; j < 2; j++) {
                        int kglob = kt0 + warp_n + nt * 8 + tg * 2 + j;
                        float s = (kglob < SEQ) ? sacc[mt][nt][hh * 2 + j] * SCALE : -1e30f;
                        sacc[mt][nt][hh * 2 + j] = s;
                        pm = fmaxf(pm, s);
                    }
                }
                pm = fmaxf(pm, __shfl_xor_sync(0xffffffffu, pm, 1));
                pm = fmaxf(pm, __shfl_xor_sync(0xffffffffu, pm, 2));
                if (tg == 0)
                    red_m[colgrp * 128 + warp_m + mt * 16 + hh * 8 + g] = pm;
            }
        }
        __syncthreads();

        #pragma unroll
        for (int mt = 0; mt < 2; mt++) {
            #pragma unroll
            for (int hh = 0; hh < 2; hh++) {
                int r = warp_m + mt * 16 + hh * 8 + g;
                float mtile = fmaxf(red_m[r], red_m[128 + r]);
                float mnew  = fmaxf(row_m[r], mtile);
                float alpha = __expf(row_m[r] - mnew);
                float psum = 0.f;
                #pragma unroll
                for (int nt = 0; nt < 4; nt++) {
                    #pragma unroll
                    for (int j = 0; j < 2; j++) {
                        float p = __expf(sacc[mt][nt][hh * 2 + j] - mnew);
                        psum += p;
                        Ps[r * 68 + warp_n + nt * 8 + tg * 2 + j] = f2tf32(p);
                        oacc[mt][nt][hh * 2 + j] *= alpha;
                    }
                }
                psum += __shfl_xor_sync(0xffffffffu, psum, 1);
                psum += __shfl_xor_sync(0xffffffffu, psum, 2);
                if (tg == 0) red_l[colgrp * 128 + r] = psum;
            }
        }
        __syncthreads();

        if (tid < 128) {
            int r = tid;
            float mtile = fmaxf(red_m[r], red_m[128 + r]);
            float mold = row_m[r];
            float mnew = fmaxf(mold, mtile);
            row_l[r] = __expf(mold - mnew) * row_l[r] + red_l[r] + red_l[128 + r];
            row_m[r] = mnew;
        }

        #pragma unroll
        for (int ks = 0; ks < 8; ks++) {
            const int kk = ks * 8;
            uint32_t af[2][4];
            #pragma unroll
            for (int mt = 0; mt < 2; mt++) {
                int rs = warp_m + mt * 16 + g;
                af[mt][0] = Ps[rs * 68 + kk + tg];
                af[mt][1] = Ps[(rs + 8) * 68 + kk + tg];
                af[mt][2] = Ps[rs * 68 + kk + tg + 4];
                af[mt][3] = Ps[(rs + 8) * 68 + kk + tg + 4];
            }
            uint32_t bf[4][2];
            #pragma unroll
            for (int nt = 0; nt < 4; nt++) {
                int cs = warp_n + nt * 8 + g;
                bf[nt][0] = Vs[cs * 68 + kk + tg];
                bf[nt][1] = Vs[cs * 68 + kk + tg + 4];
            }
            #pragma unroll
            for (int mt = 0; mt < 2; mt++)
                #pragma unroll
                for (int nt = 0; nt < 4; nt++)
                    mma_tf32(oacc[mt][nt], af[mt], bf[nt]);
        }
        __syncthreads();
    }

    #pragma unroll
    for (int mt = 0; mt < 2; mt++) {
        #pragma unroll
        for (int hh = 0; hh < 2; hh++) {
            int r = warp_m + mt * 16 + hh * 8 + g;
            int t = q0 + r;
            if (t >= SEQ) continue;
            float inv = 1.f / row_l[r];
            #pragma unroll
            for (int nt = 0; nt < 4; nt++) {
                #pragma unroll
                for (int j = 0; j < 2; j++) {
                    int c = warp_n + nt * 8 + tg * 2 + j;
                    ATT[((long long)(b * SEQ + t)) * DM + h * HS + c] =
                        oacc[mt][nt][hh * 2 + j] * inv;
                }
            }
        }
    }
}

// ---------------------------------------------------------------------------
// LayerNorm
// ---------------------------------------------------------------------------
__global__ void __launch_bounds__(256)
ln_k(const float* __restrict__ x, float* __restrict__ out,
     const float* __restrict__ g, const float* __restrict__ b,
     long long strideIn, long long strideOut)
{
    long long r = blockIdx.x;
    const float* xr = x + r * strideIn;
    float* orow = out + r * strideOut;

    float s = 0.f, s2 = 0.f;
    for (int i = threadIdx.x; i < DM; i += 256) {
        float v = xr[i]; s += v; s2 += v * v;
    }
    for (int o = 16; o; o >>= 1) {
        s  += __shfl_down_sync(0xffffffffu, s,  o);
        s2 += __shfl_down_sync(0xffffffffu, s2, o);
    }
    __shared__ float shs[8], shs2[8];
    int w = threadIdx.x >> 5, ln = threadIdx.x & 31;
    if (ln == 0) { shs[w] = s; shs2[w] = s2; }
    __syncthreads();
    __shared__ float sh_m, sh_inv;
    if (threadIdx.x == 0) {
        float S = 0.f, S2 = 0.f;
        #pragma unroll
        for (int i = 0; i < 8; i++) { S += shs[i]; S2 += shs2[i]; }
        float m = S / (float)DM;
        float var = S2 / (float)DM - m * m;
        sh_m = m; sh_inv = rsqrtf(var + 1e-5f);
    }
    __syncthreads();
    float m = sh_m, inv = sh_inv;
    for (int i = threadIdx.x; i < DM; i += 256)
        orow[i] = (xr[i] - m) * inv * g[i] + b[i];
}

// ---------------------------------------------------------------------------
// Patchify / scatter / embed
// ---------------------------------------------------------------------------
__global__ void patchify_k(const float* __restrict__ img, float* __restrict__ P)
{
    int idx = blockIdx.x * blockDim.x + threadIdx.x;
    if (idx >= BATCH * NPATCH * DM) return;
    int d = idx % DM;
    int p = (idx / DM) % NPATCH;
    int b = idx / (DM * NPATCH);
    int c   = d % 3;
    int pix = d / 3;
    int px  = pix % PATCH, py = pix / PATCH;
    int pw  = p % 14,      ph = p / 14;
    int row = ph * PATCH + py, col = pw * PATCH + px;
    P[idx] = img[(((long long)b * IMG + row) * IMG + col) * 3 + c];
}

__global__ void scatter_patch_k(const float* __restrict__ G, float* __restrict__ X,
                                const float* __restrict__ pb,
                                const float* __restrict__ pos, int tokoff)
{
    int idx = blockIdx.x * blockDim.x + threadIdx.x;
    if (idx >= BATCH * NPATCH * DM) return;
    int d = idx % DM;
    int r = idx / DM;
    int b = r / NPATCH, p = r % NPATCH;
    int t = tokoff + p;
    X[((long long)b * SEQ + t) * DM + d] = G[idx] + pb[d] + pos[(long long)t * DM + d];
}

__global__ void embed_special_k(float* __restrict__ X,
                                const float* __restrict__ cls,
                                const float* __restrict__ goal,
                                const float* __restrict__ tok_emb,
                                const int*   __restrict__ txt,
                                const float* __restrict__ pos)
{
    int idx = blockIdx.x * blockDim.x + threadIdx.x;
    if (idx >= BATCH * 34 * DM) return;
    int d = idx % DM;
    int s = (idx / DM) % 34;
    int b = idx / (DM * 34);
    int t; float v;
    if (s == 0)      { t = 0;   v = cls[d];  }
    else if (s == 1) { t = 197; v = goal[d]; }
    else {
        t = 394 + (s - 2);
        v = tok_emb[(long long)txt[b * TB + (s - 2)] * DM + d];
    }
    X[((long long)b * SEQ + t) * DM + d] = v + pos[(long long)t * DM + d];
}

// ---------------------------------------------------------------------------
// Host driver
// ---------------------------------------------------------------------------
static inline dim3 dgrid(int M, int N) {
    return dim3((unsigned)(N / 192), (unsigned)((M + 127) / 128), 1);
}

extern "C" void kernel_launch(void* const* d_in, const int* in_sizes, int n_in,
                              void* d_out, int out_size)
{
    (void)in_sizes; (void)n_in; (void)out_size;

    const float* images    = (const float*)d_in[0];
    const float* goal_imgs = (const float*)d_in[1];
    const int*   goals_txt = (const int*)  d_in[2];
    const float* patch_W   = (const float*)d_in[3];
    const float* patch_b   = (const float*)d_in[4];
    const float* tok_emb   = (const float*)d_in[5];
    const float* pos_emb   = (const float*)d_in[6];
    const float* cls_tok   = (const float*)d_in[7];
    const float* goal_tok  = (const float*)d_in[8];
    const float* Wq        = (const float*)d_in[9];
    const float* Wk        = (const float*)d_in[10];
    const float* Wv        = (const float*)d_in[11];
    const float* Wo        = (const float*)d_in[12];
    const float* bo        = (const float*)d_in[13];
    const float* ln1_g     = (const float*)d_in[14];
    const float* ln1_b     = (const float*)d_in[15];
    const float* ln2_g     = (const float*)d_in[16];
    const float* ln2_b     = (const float*)d_in[17];
    const float* W1        = (const float*)d_in[18];
    const float* b1        = (const float*)d_in[19];
    const float* W2        = (const float*)d_in[20];
    const float* b2        = (const float*)d_in[21];
    const float* lnf_g     = (const float*)d_in[22];
    const float* lnf_b     = (const float*)d_in[23];
    const float* ah_W1     = (const float*)d_in[24];
    const float* ah_b1     = (const float*)d_in[25];
    const float* ah_W2     = (const float*)d_in[26];
    const float* ah_b2     = (const float*)d_in[27];
    float* out = (float*)d_out;

    float *X, *XN, *Qf, *Kf, *Vf, *ATT, *H, *P, *CLS, *HID;
    cudaGetSymbolAddress((void**)&X,   g_X);
    cudaGetSymbolAddress((void**)&XN,  g_XN);
    cudaGetSymbolAddress((void**)&Qf,  g_Q);
    cudaGetSymbolAddress((void**)&Kf,  g_K);
    cudaGetSymbolAddress((void**)&Vf,  g_V);
    cudaGetSymbolAddress((void**)&ATT, g_ATT);
    cudaGetSymbolAddress((void**)&H,   g_H);
    cudaGetSymbolAddress((void**)&P,   g_P);
    cudaGetSymbolAddress((void**)&CLS, g_CLS);
    cudaGetSymbolAddress((void**)&HID, g_HID);

    const int PTOT = BATCH * NPATCH * DM;
    const int FSMEM = FLASH_SMEM_WORDS * 4;
    cudaFuncSetAttribute(flash_attn_k, cudaFuncAttributeMaxDynamicSharedMemorySize, FSMEM);
    cudaFuncSetAttribute(gemm_dual<false,false,false,false>, cudaFuncAttributeMaxDynamicSharedMemorySize, DUAL_SMEM);
    cudaFuncSetAttribute(gemm_dual<true ,false,false,false>, cudaFuncAttributeMaxDynamicSharedMemorySize, DUAL_SMEM);
    cudaFuncSetAttribute(gemm_dual<false,false,true ,true >, cudaFuncAttributeMaxDynamicSharedMemorySize, DUAL_SMEM);
    cudaFuncSetAttribute(gemm_dual<false,true ,false,true >, cudaFuncAttributeMaxDynamicSharedMemorySize, DUAL_SMEM);

    // --- Embedding ---------------------------------------------------------
    patchify_k<<<(PTOT + 255) / 256, 256>>>(images, P);
    gemm_dual<false,false,false,false><<<dgrid(BATCH*NPATCH, DM), 384, DUAL_SMEM>>>(
        P, patch_W, H, nullptr, BATCH*NPATCH, DM, DM, DM, DM, DM, 1.f);
    scatter_patch_k<<<(PTOT + 255) / 256, 256>>>(H, X, patch_b, pos_emb, 1);

    patchify_k<<<(PTOT + 255) / 256, 256>>>(goal_imgs, P);
    gemm_dual<false,false,false,false><<<dgrid(BATCH*NPATCH, DM), 384, DUAL_SMEM>>>(
        P, patch_W, H, nullptr, BATCH*NPATCH, DM, DM, DM, DM, DM, 1.f);
    scatter_patch_k<<<(PTOT + 255) / 256, 256>>>(H, X, patch_b, pos_emb, 198);

    embed_special_k<<<(BATCH*34*DM + 255) / 256, 256>>>(
        X, cls_tok, goal_tok, tok_emb, goals_txt, pos_emb);

    // --- Transformer layers ------------------------------------------------
    for (int l = 0; l < NL; l++) {
        const float* Wq_l  = Wq + (long long)l * NH * DM * HS;
        const float* Wk_l  = Wk + (long long)l * NH * DM * HS;
        const float* Wv_l  = Wv + (long long)l * NH * DM * HS;
        const float* Wo_l  = Wo + (long long)l * DM * DM;
        const float* bo_l  = bo + (long long)l * DM;
        const float* l1g   = ln1_g + (long long)l * DM;
        const float* l1b   = ln1_b + (long long)l * DM;
        const float* l2g   = ln2_g + (long long)l * DM;
        const float* l2b   = ln2_b + (long long)l * DM;
        const float* W1_l  = W1 + (long long)l * DM * MLPD;
        const float* b1_l  = b1 + (long long)l * MLPD;
        const float* W2_l  = W2 + (long long)l * MLPD * DM;
        const float* b2_l  = b2 + (long long)l * DM;

        ln_k<<<TOK, 256>>>(X, XN, l1g, l1b, DM, DM);

        gemm_dual<true,false,false,false><<<dgrid(TOK, DM), 384, DUAL_SMEM>>>(
            XN, Wq_l, Qf, nullptr, TOK, DM, DM, DM, DM*HS, DM, 1.f);
        gemm_dual<true,false,false,false><<<dgrid(TOK, DM), 384, DUAL_SMEM>>>(
            XN, Wk_l, Kf, nullptr, TOK, DM, DM, DM, DM*HS, DM, 1.f);
        gemm_dual<true,false,false,false><<<dgrid(TOK, DM), 384, DUAL_SMEM>>>(
            XN, Wv_l, Vf, nullptr, TOK, DM, DM, DM, DM*HS, DM, 1.f);

        flash_attn_k<<<dim3(4, BATCH*NH), 256, FSMEM>>>(Qf, Kf, Vf, ATT);

        gemm_dual<false,false,true,true><<<dgrid(TOK, DM), 384, DUAL_SMEM>>>(
            ATT, Wo_l, X, bo_l, TOK, DM, DM, DM, DM, DM, 1.f);

        ln_k<<<TOK, 256>>>(X, XN, l2g, l2b, DM, DM);

        gemm_dual<false,true,false,true><<<dgrid(TOK, MLPD), 384, DUAL_SMEM>>>(
            XN, W1_l, H, b1_l, TOK, MLPD, DM, DM, MLPD, MLPD, 1.f);

        gemm_dual<false,false,true,true><<<dgrid(TOK, DM), 384, DUAL_SMEM>>>(
            H, W2_l, X, b2_l, TOK, DM, MLPD, MLPD, DM, DM, 1.f);
    }

    // --- Final LN (cls rows only) + action head ---------------------------
    ln_k<<<BATCH, 256>>>(X, CLS, lnf_g, lnf_b, (long long)SEQ * DM, DM);

    gemm_dual<false,true,false,true><<<dgrid(BATCH, 4*DM), 384, DUAL_SMEM>>>(
        CLS, ah_W1, HID, ah_b1, BATCH, 4*DM, DM, DM, 4*DM, 4*DM, 1.f);

    gemm_tf32<64,false,false,false,false,true><<<dim3(1, 1, 1), 256>>>(
        HID, ah_W2, out, ah_b2, BATCH, AOUT, 4*DM, 4*DM, AOUT, AOUT, 1.f,
        1, 0,0, 0,0, 0,0);
}